// round 14
// baseline (speedup 1.0000x reference)
#include <cuda_runtime.h>
#include <cuda_fp16.h>
#include <math.h>

#define B_ROWS 4096
#define T_LEN  8192
#define SCAN_THREADS 512
#define NWARPS (SCAN_THREADS / 32)     // 16
#define CHUNK (T_LEN / SCAN_THREADS)   // 16
#define GROUPS (T_LEN / 4)             // 2048 float4-groups per row
#define GAMMA 0.99f
#define GAMMA16 0.8514577710948755f    // 0.99^16
#define EPS_N 1e-9f
#define RPAD 513                       // padded row stride (words) for transpose smem
#define NCTA (148 * 3)                 // persistent grid; all CTAs co-resident @occ3

// Scratch (device globals; no allocations allowed). All zero-init; every
// counter/flag returns to 0 by end of launch -> graph-replay deterministic.
__device__ float    g_row_sum[B_ROWS];
__device__ float    g_row_inv[B_ROWS];
__device__ float    g_mean_val;
__device__ unsigned g_count;           // scan tickets: wraps at B_ROWS
__device__ unsigned g_done;            // phase-2 tickets: wraps at NCTA
__device__ unsigned g_flag;            // gmean-ready; last phase-2 CTA clears
// fp16 staging for unnormalized returns: 64 MB, L2-resident in steady state.
__device__ __align__(128) __half g_ret_h[(size_t)B_ROWS * T_LEN];

// ───────── fused: scan all own rows → grid barrier (gmean) → norm own rows ─────────
__global__ __launch_bounds__(SCAN_THREADS, 3)
void fused_kernel(const float* __restrict__ rewards,
                  const float* __restrict__ dones,
                  float* __restrict__ out)
{
    const int tid  = threadIdx.x;
    const int lane = tid & 31;
    const int wid  = tid >> 5;

    __shared__ float s_rew[16 * RPAD];
    __shared__ __align__(16) unsigned s_db[GROUPS];
    __shared__ float sWA[NWARPS], sWB[NWARPS], sCB[NWARPS];
    __shared__ float sS[NWARPS],  sQ[NWARPS];
    __shared__ unsigned s_last;

    // ════════ Phase 1: scan rows bid, bid+NCTA, ... (R13-proven body) ════════
    for (int row = blockIdx.x; row < B_ROWS; row += NCTA) {
        const size_t row_off = (size_t)row * T_LEN;

        const float4* r4 = reinterpret_cast<const float4*>(rewards + row_off);
        const float4* d4 = reinterpret_cast<const float4*>(dones   + row_off);
#pragma unroll
        for (int k = 0; k < 4; k++) {
            const int g = tid + 512 * k;
            float4 rv = __ldcs(r4 + g);
            float4 dv = __ldcs(d4 + g);
            const int c = (g & 3) * 4;
            const int q = g >> 2;
            s_rew[(c + 0) * RPAD + q] = rv.x;
            s_rew[(c + 1) * RPAD + q] = rv.y;
            s_rew[(c + 2) * RPAD + q] = rv.z;
            s_rew[(c + 3) * RPAD + q] = rv.w;
            unsigned p = (dv.x != 0.0f ? 1u : 0u)
                       | (dv.y != 0.0f ? 1u : 0u) << 8
                       | (dv.z != 0.0f ? 1u : 0u) << 16
                       | (dv.w != 0.0f ? 1u : 0u) << 24;
            s_db[g] = p;
        }
        __syncthreads();

        unsigned mask = 0;
        {
            const uint4 dw = *reinterpret_cast<const uint4*>(&s_db[tid * 4]);
            const unsigned w[4] = {dw.x, dw.y, dw.z, dw.w};
#pragma unroll
            for (int q = 0; q < 4; q++) {
                mask |= ((w[q] >> 0)  & 1u) << (4*q + 0);
                mask |= ((w[q] >> 8)  & 1u) << (4*q + 1);
                mask |= ((w[q] >> 16) & 1u) << (4*q + 2);
                mask |= ((w[q] >> 24) & 1u) << (4*q + 3);
            }
        }

        float A  = (mask == 0u) ? GAMMA16 : 0.0f;
        float Bc = 0.0f;
#pragma unroll
        for (int t = CHUNK - 1; t >= 0; t--) {
            float v = s_rew[t * RPAD + tid];
            float f = fmaf(GAMMA, Bc, v);
            Bc = (mask & (1u << t)) ? v : f;
        }

#pragma unroll
        for (int d = 1; d < 32; d <<= 1) {
            float A2 = __shfl_down_sync(0xFFFFFFFFu, A, d);
            float B2 = __shfl_down_sync(0xFFFFFFFFu, Bc, d);
            if (lane + d < 32) {
                Bc = fmaf(A, B2, Bc);
                A  = A * A2;
            }
        }

        if (lane == 0) { sWA[wid] = A; sWB[wid] = Bc; }
        __syncthreads();

        if (wid == 0) {
            float wA = (lane < NWARPS) ? sWA[lane] : 1.0f;
            float wB = (lane < NWARPS) ? sWB[lane] : 0.0f;
#pragma unroll
            for (int d = 1; d < NWARPS; d <<= 1) {
                float A2 = __shfl_down_sync(0xFFFFFFFFu, wA, d);
                float B2 = __shfl_down_sync(0xFFFFFFFFu, wB, d);
                if (lane + d < NWARPS) {
                    wB = fmaf(wA, B2, wB);
                    wA = wA * A2;
                }
            }
            float eB = __shfl_down_sync(0xFFFFFFFFu, wB, 1);
            if (lane == NWARPS - 1) eB = 0.0f;
            if (lane < NWARPS) sCB[lane] = eB;
        }
        __syncthreads();

        float cB   = sCB[wid];
        float totB = fmaf(A, cB, Bc);
        float carry = __shfl_down_sync(0xFFFFFFFFu, totB, 1);
        if (lane == 31) carry = cB;

        float sum = 0.0f, sq = 0.0f;
#pragma unroll
        for (int t = CHUNK - 1; t >= 0; t--) {
            float v = s_rew[t * RPAD + tid];
            float f = fmaf(GAMMA, carry, v);
            carry = (mask & (1u << t)) ? v : f;
            s_rew[t * RPAD + tid] = carry;
            sum += carry;
            sq = fmaf(carry, carry, sq);
        }

        {
            __half2 h[CHUNK / 2];
#pragma unroll
            for (int i = 0; i < CHUNK / 2; i++)
                h[i] = __floats2half2_rn(s_rew[(2*i) * RPAD + tid],
                                         s_rew[(2*i+1) * RPAD + tid]);
            uint4* dst = reinterpret_cast<uint4*>(g_ret_h + row_off + tid * CHUNK);
            const uint4* srcv = reinterpret_cast<const uint4*>(h);
            dst[0] = srcv[0];
            dst[1] = srcv[1];
        }

#pragma unroll
        for (int d = 16; d > 0; d >>= 1) {
            sum += __shfl_down_sync(0xFFFFFFFFu, sum, d);
            sq  += __shfl_down_sync(0xFFFFFFFFu, sq,  d);
        }
        if (lane == 0) { sS[wid] = sum; sQ[wid] = sq; }
        __syncthreads();
        if (tid < 32) {
            float ts = (lane < NWARPS) ? sS[lane] : 0.0f;
            float tq = (lane < NWARPS) ? sQ[lane] : 0.0f;
#pragma unroll
            for (int d = NWARPS / 2; d > 0; d >>= 1) {
                ts += __shfl_down_sync(0xFFFFFFFFu, ts, d);
                tq += __shfl_down_sync(0xFFFFFFFFu, tq, d);
            }
            if (lane == 0) {
                float mean = ts / (float)T_LEN;
                float var  = (tq - ts * mean) / (float)(T_LEN - 1);   // ddof=1
                g_row_sum[row] = ts;
                g_row_inv[row] = 1.0f / (sqrtf(fmaxf(var, 0.0f)) + EPS_N);
            }
        }

        // Per-row completion ticket; final ticket computes gmean and raises flag.
        if (tid == 0) {
            __threadfence();
            unsigned prev = atomicInc(&g_count, B_ROWS - 1);   // wraps -> self-reset
            s_last = (prev == B_ROWS - 1) ? 1u : 0u;
        }
        __syncthreads();
        if (s_last) {
            float s = 0.0f;
#pragma unroll
            for (int i = 0; i < B_ROWS / SCAN_THREADS; i++)
                s += __ldcg(&g_row_sum[tid + i * SCAN_THREADS]);
#pragma unroll
            for (int d = 16; d > 0; d >>= 1)
                s += __shfl_down_sync(0xFFFFFFFFu, s, d);
            if (lane == 0) sS[wid] = s;
            __syncthreads();
            if (tid < 32) {
                float t = (lane < NWARPS) ? sS[lane] : 0.0f;
#pragma unroll
                for (int d = 16; d > 0; d >>= 1)
                    t += __shfl_down_sync(0xFFFFFFFFu, t, d);
                if (tid == 0) {
                    g_mean_val = t / ((float)B_ROWS * (float)T_LEN);
                    __threadfence();
                    atomicExch(&g_flag, 1u);       // gmean ready
                }
            }
            __syncthreads();
        }
    }

    // ════════ Grid barrier + Phase 2: normalize own rows ════════
    // Prefetch the first tile's staging loads BEFORE spinning: they don't
    // depend on gmean, so they stream in while we wait.
    const int row0 = blockIdx.x;
    const uint2* src = reinterpret_cast<const uint2*>(g_ret_h);
    float4* o4 = reinterpret_cast<float4*>(out);

    uint2 p[4];
    {
        const size_t unit0 = (size_t)row0 * GROUPS + tid;
#pragma unroll
        for (int k = 0; k < 4; k++)
            p[k] = __ldlu(src + unit0 + 512 * k);
    }

    // Spin until gmean is published (all CTAs co-resident -> no deadlock).
    if (tid == 0) {
        while (atomicAdd(&g_flag, 0u) == 0u) __nanosleep(128);
    }
    __syncthreads();
    __threadfence();                       // acquire: gmean/row_inv visible
    const float gmean = __ldcg(&g_mean_val);

    for (int row = row0; row < B_ROWS; row += NCTA) {
        const float inv = __ldcg(&g_row_inv[row]);
        const float neg = -gmean * inv;
        const size_t unit0 = (size_t)row * GROUPS + tid;

        if (row != row0) {
#pragma unroll
            for (int k = 0; k < 4; k++)
                p[k] = __ldlu(src + unit0 + 512 * k);
        }
#pragma unroll
        for (int k = 0; k < 4; k++) {
            __half2 h0 = *reinterpret_cast<__half2*>(&p[k].x);
            __half2 h1 = *reinterpret_cast<__half2*>(&p[k].y);
            float2 a = __half22float2(h0);
            float2 b = __half22float2(h1);
            float4 v;
            v.x = fmaf(a.x, inv, neg);
            v.y = fmaf(a.y, inv, neg);
            v.z = fmaf(b.x, inv, neg);
            v.w = fmaf(b.y, inv, neg);
            __stcs(o4 + unit0 + 512 * k, v);
        }
    }

    // Phase-2 exit ticket: last CTA clears the flag (self-reset for replay).
    if (tid == 0) {
        __threadfence();
        unsigned prev = atomicInc(&g_done, NCTA - 1);   // wraps -> self-reset
        if (prev == NCTA - 1)
            atomicExch(&g_flag, 0u);
    }
}

extern "C" void kernel_launch(void* const* d_in, const int* in_sizes, int n_in,
                              void* d_out, int out_size)
{
    const float* rewards = (const float*)d_in[0];
    const float* dones   = (const float*)d_in[1];
    float* out = (float*)d_out;

    fused_kernel<<<NCTA, SCAN_THREADS>>>(rewards, dones, out);
}

// round 15
// speedup vs baseline: 1.1274x; 1.1274x over previous
#include <cuda_runtime.h>
#include <cuda_fp16.h>
#include <math.h>

#define B_ROWS 4096
#define T_LEN  8192
#define SCAN_THREADS 512
#define NWARPS (SCAN_THREADS / 32)     // 16
#define CHUNK (T_LEN / SCAN_THREADS)   // 16
#define GROUPS (T_LEN / 4)             // 2048 float4-groups per row
#define GAMMA 0.99f
#define GAMMA16 0.8514577710948755f    // 0.99^16
#define EPS_N 1e-9f
#define RPAD 513                       // padded row stride (words) for transpose smem

// Scratch (device globals; no allocations allowed).
__device__ float    g_row_sum[B_ROWS];
__device__ float    g_row_inv[B_ROWS];
__device__ float    g_mean_val;
__device__ unsigned g_count;           // zero-init; atomicInc wraps -> self-reset per launch
// fp16 staging for unnormalized returns: 64 MB, L2-resident in steady state.
__device__ __align__(128) __half g_ret_h[(size_t)B_ROWS * T_LEN];

// ───────────────────────── scan: one block per row ─────────────────────────
// x_t = r_t + a_t * x_{t+1},  a_t = GAMMA*(1-done_t),  done in {0,1} exactly.
// R13-proven: values live in smem (transposed), 32 regs -> 4 CTAs/SM.
__global__ __launch_bounds__(SCAN_THREADS, 4)
void scan_kernel(const float* __restrict__ rewards,
                 const float* __restrict__ dones)
{
    const int row  = blockIdx.x;
    const int tid  = threadIdx.x;
    const int lane = tid & 31;
    const int wid  = tid >> 5;
    const size_t row_off = (size_t)row * T_LEN;

    __shared__ float s_rew[16 * RPAD];          // transposed values (in-place updated)
    __shared__ __align__(16) unsigned s_db[GROUPS];  // 4 done-bytes packed per word
    __shared__ float sWA[NWARPS], sWB[NWARPS], sCB[NWARPS];
    __shared__ float sS[NWARPS],  sQ[NWARPS];
    __shared__ unsigned s_last;

    // ── Phase 1: coalesced load (lane-contiguous float4 groups) -> smem ──
    const float4* r4 = reinterpret_cast<const float4*>(rewards + row_off);
    const float4* d4 = reinterpret_cast<const float4*>(dones   + row_off);
#pragma unroll
    for (int k = 0; k < 4; k++) {
        const int g = tid + 512 * k;
        float4 rv = __ldcs(r4 + g);
        float4 dv = __ldcs(d4 + g);
        const int c = (g & 3) * 4;
        const int q = g >> 2;
        s_rew[(c + 0) * RPAD + q] = rv.x;
        s_rew[(c + 1) * RPAD + q] = rv.y;
        s_rew[(c + 2) * RPAD + q] = rv.z;
        s_rew[(c + 3) * RPAD + q] = rv.w;
        unsigned p = (dv.x != 0.0f ? 1u : 0u)
                   | (dv.y != 0.0f ? 1u : 0u) << 8
                   | (dv.z != 0.0f ? 1u : 0u) << 16
                   | (dv.w != 0.0f ? 1u : 0u) << 24;
        s_db[g] = p;
    }
    __syncthreads();

    // ── Phase 2: compose chunk affine map, reading values from smem ──
    unsigned mask = 0;
    {
        const uint4 dw = *reinterpret_cast<const uint4*>(&s_db[tid * 4]);
        const unsigned w[4] = {dw.x, dw.y, dw.z, dw.w};
#pragma unroll
        for (int q = 0; q < 4; q++) {
            mask |= ((w[q] >> 0)  & 1u) << (4*q + 0);
            mask |= ((w[q] >> 8)  & 1u) << (4*q + 1);
            mask |= ((w[q] >> 16) & 1u) << (4*q + 2);
            mask |= ((w[q] >> 24) & 1u) << (4*q + 3);
        }
    }

    float A  = (mask == 0u) ? GAMMA16 : 0.0f;
    float Bc = 0.0f;
#pragma unroll
    for (int t = CHUNK - 1; t >= 0; t--) {
        float v = s_rew[t * RPAD + tid];        // conflict-free (lane-contiguous)
        float f = fmaf(GAMMA, Bc, v);
        Bc = (mask & (1u << t)) ? v : f;
    }

    // Warp-level inclusive SUFFIX scan via shuffles.
#pragma unroll
    for (int d = 1; d < 32; d <<= 1) {
        float A2 = __shfl_down_sync(0xFFFFFFFFu, A, d);
        float B2 = __shfl_down_sync(0xFFFFFFFFu, Bc, d);
        if (lane + d < 32) {
            Bc = fmaf(A, B2, Bc);
            A  = A * A2;
        }
    }

    if (lane == 0) { sWA[wid] = A; sWB[wid] = Bc; }
    __syncthreads();

    if (wid == 0) {
        float wA = (lane < NWARPS) ? sWA[lane] : 1.0f;
        float wB = (lane < NWARPS) ? sWB[lane] : 0.0f;
#pragma unroll
        for (int d = 1; d < NWARPS; d <<= 1) {
            float A2 = __shfl_down_sync(0xFFFFFFFFu, wA, d);
            float B2 = __shfl_down_sync(0xFFFFFFFFu, wB, d);
            if (lane + d < NWARPS) {
                wB = fmaf(wA, B2, wB);
                wA = wA * A2;
            }
        }
        float eB = __shfl_down_sync(0xFFFFFFFFu, wB, 1);
        if (lane == NWARPS - 1) eB = 0.0f;
        if (lane < NWARPS) sCB[lane] = eB;
    }
    __syncthreads();

    float cB   = sCB[wid];
    float totB = fmaf(A, cB, Bc);
    float carry = __shfl_down_sync(0xFFFFFFFFu, totB, 1);
    if (lane == 31) carry = cB;        // tid==511 -> cB==0, correct

    // ── Phase 3: replay from smem, write carries back IN PLACE ──
    float sum = 0.0f, sq = 0.0f;
#pragma unroll
    for (int t = CHUNK - 1; t >= 0; t--) {
        float v = s_rew[t * RPAD + tid];
        float f = fmaf(GAMMA, carry, v);
        carry = (mask & (1u << t)) ? v : f;
        s_rew[t * RPAD + tid] = carry;
        sum += carry;
        sq = fmaf(carry, carry, sq);
    }

    // ── Phase 4: re-read own values, pack fp16, thread-contiguous store ──
    {
        __half2 h[CHUNK / 2];
#pragma unroll
        for (int i = 0; i < CHUNK / 2; i++)
            h[i] = __floats2half2_rn(s_rew[(2*i) * RPAD + tid],
                                     s_rew[(2*i+1) * RPAD + tid]);
        uint4* dst = reinterpret_cast<uint4*>(g_ret_h + row_off + tid * CHUNK);
        const uint4* srcv = reinterpret_cast<const uint4*>(h);
        dst[0] = srcv[0];
        dst[1] = srcv[1];
    }

    // Block reduction of (sum, sq).
#pragma unroll
    for (int d = 16; d > 0; d >>= 1) {
        sum += __shfl_down_sync(0xFFFFFFFFu, sum, d);
        sq  += __shfl_down_sync(0xFFFFFFFFu, sq,  d);
    }
    if (lane == 0) { sS[wid] = sum; sQ[wid] = sq; }
    __syncthreads();
    if (tid < 32) {
        float ts = (lane < NWARPS) ? sS[lane] : 0.0f;
        float tq = (lane < NWARPS) ? sQ[lane] : 0.0f;
#pragma unroll
        for (int d = NWARPS / 2; d > 0; d >>= 1) {
            ts += __shfl_down_sync(0xFFFFFFFFu, ts, d);
            tq += __shfl_down_sync(0xFFFFFFFFu, tq, d);
        }
        if (lane == 0) {
            float mean = ts / (float)T_LEN;
            float var  = (tq - ts * mean) / (float)(T_LEN - 1);   // ddof=1
            g_row_sum[row] = ts;
            g_row_inv[row] = 1.0f / (sqrtf(fmaxf(var, 0.0f)) + EPS_N);
        }
    }

    // Last block to finish reduces the 4096 row sums -> global mean.
    if (tid == 0) {
        __threadfence();
        unsigned prev = atomicInc(&g_count, B_ROWS - 1);   // wraps to 0: self-reset
        s_last = (prev == B_ROWS - 1) ? 1u : 0u;
    }
    __syncthreads();
    if (s_last) {
        float s = 0.0f;
#pragma unroll
        for (int i = 0; i < B_ROWS / SCAN_THREADS; i++)
            s += __ldcg(&g_row_sum[tid + i * SCAN_THREADS]);
#pragma unroll
        for (int d = 16; d > 0; d >>= 1)
            s += __shfl_down_sync(0xFFFFFFFFu, s, d);
        if (lane == 0) sS[wid] = s;
        __syncthreads();
        if (tid < 32) {
            float t = (lane < NWARPS) ? sS[lane] : 0.0f;
#pragma unroll
            for (int d = 16; d > 0; d >>= 1)
                t += __shfl_down_sync(0xFFFFFFFFu, t, d);
            if (tid == 0)
                g_mean_val = t / ((float)B_ROWS * (float)T_LEN);
        }
    }
}

// ── normalize: half-row per CTA (grid 8192 × 256) — finer tail granularity.
// Per-thread work identical to R13: 4 unit-interleaved __ldlu loads (unit = 4
// elements, stride 256 units), fmaf, __stcs. Coalescing unchanged. ──
#define NORM_TPB 256
__global__ __launch_bounds__(NORM_TPB)
void norm_kernel(float* __restrict__ out)
{
    const int half = blockIdx.x;               // 0..8191: half-row tiles
    const int row  = half >> 1;
    const float inv = g_row_inv[row];
    const float neg = -g_mean_val * inv;
    // half-row = 1024 units; this CTA covers units [half*1024, half*1024+1024)
    const size_t unit0 = (size_t)half * 1024 + threadIdx.x;

    const uint2* src = reinterpret_cast<const uint2*>(g_ret_h);
    float4* o4 = reinterpret_cast<float4*>(out);

    uint2 p[4];
#pragma unroll
    for (int k = 0; k < 4; k++)
        p[k] = __ldlu(src + unit0 + NORM_TPB * k);   // front-batched, coalesced

#pragma unroll
    for (int k = 0; k < 4; k++) {
        __half2 h0 = *reinterpret_cast<__half2*>(&p[k].x);
        __half2 h1 = *reinterpret_cast<__half2*>(&p[k].y);
        float2 a = __half22float2(h0);
        float2 b = __half22float2(h1);
        float4 v;
        v.x = fmaf(a.x, inv, neg);
        v.y = fmaf(a.y, inv, neg);
        v.z = fmaf(b.x, inv, neg);
        v.w = fmaf(b.y, inv, neg);
        __stcs(o4 + unit0 + NORM_TPB * k, v);
    }
}

extern "C" void kernel_launch(void* const* d_in, const int* in_sizes, int n_in,
                              void* d_out, int out_size)
{
    const float* rewards = (const float*)d_in[0];
    const float* dones   = (const float*)d_in[1];
    float* out = (float*)d_out;

    scan_kernel<<<B_ROWS, SCAN_THREADS>>>(rewards, dones);
    norm_kernel<<<B_ROWS * 2, NORM_TPB>>>(out);
}

// round 16
// speedup vs baseline: 1.1592x; 1.0281x over previous
#include <cuda_runtime.h>
#include <cuda_fp16.h>
#include <math.h>

#define B_ROWS 4096
#define T_LEN  8192
#define SCAN_THREADS 512
#define NWARPS (SCAN_THREADS / 32)     // 16
#define CHUNK (T_LEN / SCAN_THREADS)   // 16
#define GROUPS (T_LEN / 4)             // 2048 float4-groups per row
#define GAMMA 0.99f
#define GAMMA16 0.8514577710948755f    // 0.99^16
#define EPS_N 1e-9f
#define RPAD 513                       // padded row stride (words) for transpose smem

// Scratch (device globals; no allocations allowed).
__device__ float    g_row_sum[B_ROWS];
__device__ float    g_row_inv[B_ROWS];
__device__ float    g_mean_val;
__device__ unsigned g_count;           // zero-init; atomicInc wraps -> self-reset per launch
// fp16 staging for unnormalized returns: 64 MB, L2-resident in steady state.
__device__ __align__(128) __half g_ret_h[(size_t)B_ROWS * T_LEN];

// ───────────────────────── scan: one block per row ─────────────────────────
// x_t = r_t + a_t * x_{t+1},  a_t = GAMMA*(1-done_t),  done in {0,1} exactly.
// R13 core (smem-resident values, 32 regs, 4 CTAs/SM) + inline fp16 packing in
// the replay loop: no carry writeback to smem, no re-read.
__global__ __launch_bounds__(SCAN_THREADS, 4)
void scan_kernel(const float* __restrict__ rewards,
                 const float* __restrict__ dones)
{
    const int row  = blockIdx.x;
    const int tid  = threadIdx.x;
    const int lane = tid & 31;
    const int wid  = tid >> 5;
    const size_t row_off = (size_t)row * T_LEN;

    __shared__ float s_rew[16 * RPAD];          // transposed reward values
    __shared__ __align__(16) unsigned s_db[GROUPS];  // 4 done-bytes packed per word
    __shared__ float sWA[NWARPS], sWB[NWARPS], sCB[NWARPS];
    __shared__ float sS[NWARPS],  sQ[NWARPS];
    __shared__ unsigned s_last;

    // ── Phase 1: coalesced load (lane-contiguous float4 groups) -> smem ──
    const float4* r4 = reinterpret_cast<const float4*>(rewards + row_off);
    const float4* d4 = reinterpret_cast<const float4*>(dones   + row_off);
#pragma unroll
    for (int k = 0; k < 4; k++) {
        const int g = tid + 512 * k;
        float4 rv = __ldcs(r4 + g);
        float4 dv = __ldcs(d4 + g);
        const int c = (g & 3) * 4;
        const int q = g >> 2;
        s_rew[(c + 0) * RPAD + q] = rv.x;
        s_rew[(c + 1) * RPAD + q] = rv.y;
        s_rew[(c + 2) * RPAD + q] = rv.z;
        s_rew[(c + 3) * RPAD + q] = rv.w;
        unsigned p = (dv.x != 0.0f ? 1u : 0u)
                   | (dv.y != 0.0f ? 1u : 0u) << 8
                   | (dv.z != 0.0f ? 1u : 0u) << 16
                   | (dv.w != 0.0f ? 1u : 0u) << 24;
        s_db[g] = p;
    }
    __syncthreads();

    // ── Phase 2: compose chunk affine map, reading values from smem ──
    unsigned mask = 0;
    {
        const uint4 dw = *reinterpret_cast<const uint4*>(&s_db[tid * 4]);
        const unsigned w[4] = {dw.x, dw.y, dw.z, dw.w};
#pragma unroll
        for (int q = 0; q < 4; q++) {
            mask |= ((w[q] >> 0)  & 1u) << (4*q + 0);
            mask |= ((w[q] >> 8)  & 1u) << (4*q + 1);
            mask |= ((w[q] >> 16) & 1u) << (4*q + 2);
            mask |= ((w[q] >> 24) & 1u) << (4*q + 3);
        }
    }

    float A  = (mask == 0u) ? GAMMA16 : 0.0f;
    float Bc = 0.0f;
#pragma unroll
    for (int t = CHUNK - 1; t >= 0; t--) {
        float v = s_rew[t * RPAD + tid];        // conflict-free (lane-contiguous)
        float f = fmaf(GAMMA, Bc, v);
        Bc = (mask & (1u << t)) ? v : f;
    }

    // Warp-level inclusive SUFFIX scan via shuffles.
#pragma unroll
    for (int d = 1; d < 32; d <<= 1) {
        float A2 = __shfl_down_sync(0xFFFFFFFFu, A, d);
        float B2 = __shfl_down_sync(0xFFFFFFFFu, Bc, d);
        if (lane + d < 32) {
            Bc = fmaf(A, B2, Bc);
            A  = A * A2;
        }
    }

    if (lane == 0) { sWA[wid] = A; sWB[wid] = Bc; }
    __syncthreads();

    if (wid == 0) {
        float wA = (lane < NWARPS) ? sWA[lane] : 1.0f;
        float wB = (lane < NWARPS) ? sWB[lane] : 0.0f;
#pragma unroll
        for (int d = 1; d < NWARPS; d <<= 1) {
            float A2 = __shfl_down_sync(0xFFFFFFFFu, wA, d);
            float B2 = __shfl_down_sync(0xFFFFFFFFu, wB, d);
            if (lane + d < NWARPS) {
                wB = fmaf(wA, B2, wB);
                wA = wA * A2;
            }
        }
        float eB = __shfl_down_sync(0xFFFFFFFFu, wB, 1);
        if (lane == NWARPS - 1) eB = 0.0f;
        if (lane < NWARPS) sCB[lane] = eB;
    }
    __syncthreads();

    float cB   = sCB[wid];
    float totB = fmaf(A, cB, Bc);
    float carry = __shfl_down_sync(0xFFFFFFFFu, totB, 1);
    if (lane == 31) carry = cB;        // tid==511 -> cB==0, correct

    // ── Phase 3: replay from smem with INLINE fp16 packing (t descending:
    // hold x_{2i+1}, pack h[i]=(x_{2i}, x_{2i+1}) at even t). No smem writes. ──
    float sum = 0.0f, sq = 0.0f;
    float held = 0.0f;
    __half2 h[CHUNK / 2];
#pragma unroll
    for (int t = CHUNK - 1; t >= 0; t--) {
        float v = s_rew[t * RPAD + tid];
        float f = fmaf(GAMMA, carry, v);
        carry = (mask & (1u << t)) ? v : f;
        sum += carry;
        sq = fmaf(carry, carry, sq);
        if (t & 1) held = carry;
        else       h[t >> 1] = __floats2half2_rn(carry, held);
    }

    // ── Phase 4: thread-contiguous staging store (32B/thread, 2x STG.128) ──
    {
        uint4* dst = reinterpret_cast<uint4*>(g_ret_h + row_off + tid * CHUNK);
        const uint4* srcv = reinterpret_cast<const uint4*>(h);
        dst[0] = srcv[0];
        dst[1] = srcv[1];
    }

    // Block reduction of (sum, sq).
#pragma unroll
    for (int d = 16; d > 0; d >>= 1) {
        sum += __shfl_down_sync(0xFFFFFFFFu, sum, d);
        sq  += __shfl_down_sync(0xFFFFFFFFu, sq,  d);
    }
    if (lane == 0) { sS[wid] = sum; sQ[wid] = sq; }
    __syncthreads();
    if (tid < 32) {
        float ts = (lane < NWARPS) ? sS[lane] : 0.0f;
        float tq = (lane < NWARPS) ? sQ[lane] : 0.0f;
#pragma unroll
        for (int d = NWARPS / 2; d > 0; d >>= 1) {
            ts += __shfl_down_sync(0xFFFFFFFFu, ts, d);
            tq += __shfl_down_sync(0xFFFFFFFFu, tq, d);
        }
        if (lane == 0) {
            float mean = ts / (float)T_LEN;
            float var  = (tq - ts * mean) / (float)(T_LEN - 1);   // ddof=1
            g_row_sum[row] = ts;
            g_row_inv[row] = 1.0f / (sqrtf(fmaxf(var, 0.0f)) + EPS_N);
        }
    }

    // Last block to finish reduces the 4096 row sums -> global mean.
    if (tid == 0) {
        __threadfence();
        unsigned prev = atomicInc(&g_count, B_ROWS - 1);   // wraps to 0: self-reset
        s_last = (prev == B_ROWS - 1) ? 1u : 0u;
    }
    __syncthreads();
    if (s_last) {
        float s = 0.0f;
#pragma unroll
        for (int i = 0; i < B_ROWS / SCAN_THREADS; i++)
            s += __ldcg(&g_row_sum[tid + i * SCAN_THREADS]);
#pragma unroll
        for (int d = 16; d > 0; d >>= 1)
            s += __shfl_down_sync(0xFFFFFFFFu, s, d);
        if (lane == 0) sS[wid] = s;
        __syncthreads();
        if (tid < 32) {
            float t = (lane < NWARPS) ? sS[lane] : 0.0f;
#pragma unroll
            for (int d = 16; d > 0; d >>= 1)
                t += __shfl_down_sync(0xFFFFFFFFu, t, d);
            if (tid == 0)
                g_mean_val = t / ((float)B_ROWS * (float)T_LEN);
        }
    }
}

// ── normalize: R13-proven config (best measured). One block per row; 512
// threads, 4 unit-interleaved __ldlu loads (unit = 4 elements), __stcs out. ──
__global__ __launch_bounds__(512)
void norm_kernel(float* __restrict__ out)
{
    const int row = blockIdx.x;
    const float inv = g_row_inv[row];
    const float neg = -g_mean_val * inv;
    const size_t unit0 = (size_t)row * GROUPS + threadIdx.x;

    const uint2* src = reinterpret_cast<const uint2*>(g_ret_h);
    float4* o4 = reinterpret_cast<float4*>(out);

    uint2 p[4];
#pragma unroll
    for (int k = 0; k < 4; k++)
        p[k] = __ldlu(src + unit0 + 512 * k);     // front-batched, coalesced

#pragma unroll
    for (int k = 0; k < 4; k++) {
        __half2 h0 = *reinterpret_cast<__half2*>(&p[k].x);
        __half2 h1 = *reinterpret_cast<__half2*>(&p[k].y);
        float2 a = __half22float2(h0);
        float2 b = __half22float2(h1);
        float4 v;
        v.x = fmaf(a.x, inv, neg);
        v.y = fmaf(a.y, inv, neg);
        v.z = fmaf(b.x, inv, neg);
        v.w = fmaf(b.y, inv, neg);
        __stcs(o4 + unit0 + 512 * k, v);
    }
}

extern "C" void kernel_launch(void* const* d_in, const int* in_sizes, int n_in,
                              void* d_out, int out_size)
{
    const float* rewards = (const float*)d_in[0];
    const float* dones   = (const float*)d_in[1];
    float* out = (float*)d_out;

    scan_kernel<<<B_ROWS, SCAN_THREADS>>>(rewards, dones);
    norm_kernel<<<B_ROWS, 512>>>(out);
}